// round 14
// baseline (speedup 1.0000x reference)
#include <cuda_runtime.h>
#include <cstdint>

#define B_Q    2048
#define NOBS   2048
#define PP     15
#define GG     21
#define EE     64
#define NCOL   65536          /* D*D */
#define KK     36
#define KPAD   40             /* coef gmem row stride (cols 36..39 zero, unused) */

#define BM 128                /* batch rows per CTA (MMA M) */
#define BN 128                /* S columns per CTA  (MMA N) */

// coef scratch: [b][KPAD] (tf32-rounded)
__device__ float g_coef[B_Q * KPAD];

__device__ __forceinline__ uint32_t f2tf32(float x) {
    uint32_t u;
    asm("cvt.rna.tf32.f32 %0, %1;" : "=r"(u) : "f"(x));
    return u;
}

__device__ __forceinline__ void mma_tf32(float* d, const uint32_t* a,
                                         uint32_t b0, uint32_t b1) {
    asm volatile(
        "mma.sync.aligned.m16n8k8.row.col.f32.tf32.tf32.f32 "
        "{%0,%1,%2,%3}, {%4,%5,%6,%7}, {%8,%9}, {%0,%1,%2,%3};"
        : "+f"(d[0]), "+f"(d[1]), "+f"(d[2]), "+f"(d[3])
        : "r"(a[0]), "r"(a[1]), "r"(a[2]), "r"(a[3]), "r"(b0), "r"(b1));
}
__device__ __forceinline__ void mma_tf32_k4(float* d, uint32_t a0, uint32_t a1,
                                            uint32_t b0) {
    asm volatile(
        "mma.sync.aligned.m16n8k4.row.col.f32.tf32.tf32.f32 "
        "{%0,%1,%2,%3}, {%4,%5}, {%6}, {%0,%1,%2,%3};"
        : "+f"(d[0]), "+f"(d[1]), "+f"(d[2]), "+f"(d[3])
        : "r"(a0), "r"(a1), "r"(b0));
}

// ---------------------------------------------------------------------------
// Kernel 1: warp-per-query 1-NN + alpha mixing -> g_coef[b][KPAD] (tf32-rounded)
// (unchanged from R13)
// ---------------------------------------------------------------------------
__global__ __launch_bounds__(256) void nn_coef_kernel(
    const float* __restrict__ positions, const float* __restrict__ obs_pos,
    const float* __restrict__ poly_dic,  const float* __restrict__ graph_dic,
    const float* __restrict__ alpha_poly, const float* __restrict__ alpha_graph)
{
    __shared__ float2 sObs[NOBS];
    __shared__ float  sAp[PP * PP];
    __shared__ float  sAg[EE * GG];

    const int tid = threadIdx.x;
    for (int i = tid; i < NOBS; i += 256) sObs[i] = ((const float2*)obs_pos)[i];
    for (int i = tid; i < PP * PP; i += 256) sAp[i] = alpha_poly[i];
    for (int i = tid; i < EE * GG; i += 256) sAg[i] = alpha_graph[i];
    __syncthreads();

    const int wid = tid >> 5, lid = tid & 31;
    const int b = blockIdx.x * 8 + wid;          // 256 blocks x 8 warps = 2048 queries
    const float px = positions[2 * b];
    const float py = positions[2 * b + 1];

    float bestD = 3.0e38f; int bestJ = 0;
    for (int j = lid; j < NOBS; j += 32) {
        const float dx = px - sObs[j].x;
        const float dy = py - sObs[j].y;
        const float d2 = dx * dx + dy * dy;
        if (d2 < bestD) { bestD = d2; bestJ = j; }
    }
    // exact argmin, first-index tiebreak: pack (d2bits, idx), min-reduce
    unsigned long long key = ((unsigned long long)__float_as_uint(bestD) << 32) | (unsigned)bestJ;
#pragma unroll
    for (int off = 16; off >= 1; off >>= 1) {
        unsigned long long o = __shfl_xor_sync(0xFFFFFFFFu, key, off);
        if (o < key) key = o;
    }
    const int bi = (int)(key & 0xFFFFFFFFu);

    const float* pd = poly_dic + bi * PP;
    const float* gd = graph_dic + bi * EE;
#pragma unroll
    for (int c = lid; c < KPAD; c += 32) {
        float s = 0.f;
        if (c < PP) {
#pragma unroll
            for (int q = 0; q < PP; q++) s = fmaf(pd[q], sAp[q * PP + c], s);
        } else if (c < KK) {
            const int g = c - PP;
#pragma unroll
            for (int e = 0; e < EE; e++) s = fmaf(gd[e], sAg[e * GG + g], s);
        }
        g_coef[b * KPAD + c] = __uint_as_float(f2tf32(s));
    }
}

// ---------------------------------------------------------------------------
// Kernel 2: out[b][c] = sum_k coef[b][k] * S[k][c] via mma.sync tf32.
//   EXACT R13 tiles + inner loop (123.9us proven).
//   Single change: butterfly (lane^16) epilogue exchange so every STG.128
//   covers 4 FULL 128B lines (8 lanes per row) -> store wavefronts halved.
// ---------------------------------------------------------------------------
#define SA_STRIDE 44          /* banks 12*gr+tg : all 32 distinct */
#define SS_STRIDE 136         /* slot-perm is within-64 bijective -> distinct */

__global__ __launch_bounds__(256, 3) void opd_kernel(
    const float* __restrict__ S_poly, const float* __restrict__ S_graph,
    float* __restrict__ out)
{
    __shared__ float sA[BM][SA_STRIDE];       // coef tile  [row][k] (36 used)
    __shared__ float sS[KK][SS_STRIDE];       // S tile     [k][permuted col slot]

    const int tid = threadIdx.x;
    const int wid = tid >> 5, lid = tid & 31;
    const int gr  = lid >> 2;                 // lane/4
    const int tg  = lid & 3;                  // lane%4
    const int wm  = wid >> 1;                 // M offset 32*wm
    const int wn  = wid & 1;                  // N offset 64*wn

    const int rowBase = blockIdx.x * BM;      // batch rows
    const int colBase = blockIdx.y * BN;      // S columns

    // ---- load coef tile: 128 rows x 9 float4 (36 floats; gmem stride KPAD)
#pragma unroll
    for (int i = tid; i < BM * 9; i += 256) {
        const int r = i / 9, q = i % 9;
        const float4 v = *(const float4*)&g_coef[(rowBase + r) * KPAD + q * 4];
        *(float4*)&sA[r][q * 4] = v;
    }
    // ---- S tile: 36 rows, scalar LDG + permuted scalar STS (R13 pattern)
#pragma unroll
    for (int i = tid; i < KK * BN; i += 256) {
        const int k = i >> 7, g = i & 127;
        const float* src = (k < PP) ? (S_poly + (size_t)k * NCOL)
                                    : (S_graph + (size_t)(k - PP) * NCOL);
        const float v = src[colBase + g];
        const int half = g >> 6, l = g & 63;
        const int fp = l >> 4, rem = l & 15;
        const int ptg = rem >> 2, r2 = rem & 3;
        const int s = half * 64 + (fp * 2 + (r2 >> 1)) * 8 + ptg * 2 + (r2 & 1);
        sS[k][s] = __uint_as_float(f2tf32(v));
    }
    __syncthreads();

    float d[2][8][4];
#pragma unroll
    for (int mt = 0; mt < 2; mt++)
#pragma unroll
        for (int f = 0; f < 8; f++)
#pragma unroll
            for (int j = 0; j < 4; j++) d[mt][f][j] = 0.f;

    // ---- 4 full k8 steps
#pragma unroll
    for (int ks = 0; ks < 4; ks++) {
        const int k0 = ks * 8;
        uint32_t a[2][4];
#pragma unroll
        for (int mt = 0; mt < 2; mt++) {
            const int r0 = wm * 32 + mt * 16 + gr;
            a[mt][0] = __float_as_uint(sA[r0][k0 + tg]);
            a[mt][1] = __float_as_uint(sA[r0 + 8][k0 + tg]);
            a[mt][2] = __float_as_uint(sA[r0][k0 + tg + 4]);
            a[mt][3] = __float_as_uint(sA[r0 + 8][k0 + tg + 4]);
        }
#pragma unroll
        for (int f = 0; f < 8; f++) {
            const int c0 = wn * 64 + f * 8 + gr;
            const uint32_t b0 = __float_as_uint(sS[k0 + tg][c0]);
            const uint32_t b1 = __float_as_uint(sS[k0 + tg + 4][c0]);
            mma_tf32(d[0][f], a[0], b0, b1);
            mma_tf32(d[1][f], a[1], b0, b1);
        }
    }
    // ---- k4 tail: k = 32..35
    {
        uint32_t a0[2], a1[2];
#pragma unroll
        for (int mt = 0; mt < 2; mt++) {
            const int r0 = wm * 32 + mt * 16 + gr;
            a0[mt] = __float_as_uint(sA[r0][32 + tg]);
            a1[mt] = __float_as_uint(sA[r0 + 8][32 + tg]);
        }
#pragma unroll
        for (int f = 0; f < 8; f++) {
            const int c0 = wn * 64 + f * 8 + gr;
            const uint32_t b0 = __float_as_uint(sS[32 + tg][c0]);
            mma_tf32_k4(d[0][f], a0[0], a1[0], b0);
            mma_tf32_k4(d[1][f], a0[1], a1[1], b0);
        }
    }

    // ---- epilogue with lane^16 butterfly: each STG.128 covers 4 FULL lines.
    //  Per (mt, P=line-pair, rh=row-half): lane keeps its fp=2P block, swaps
    //  its fp=2P+1 block with partner gr^4. Then:
    //   H=lo: rows rBase+rh*8+(gr&3):  gr<4 -> keep (col +0),  gr>=4 -> recv (col +16)
    //   H=hi: rows rBase+rh*8+4+(gr&3): gr<4 -> recv (col +16), gr>=4 -> keep (col +0)
    {
        const bool hiGr = (gr >= 4);
        const int rsel = gr & 3;
#pragma unroll
        for (int mt = 0; mt < 2; mt++) {
            const int rBase = rowBase + wm * 32 + mt * 16;
#pragma unroll
            for (int P = 0; P < 2; P++) {
                const int colL = colBase + wn * 64 + P * 32 + tg * 4;
#pragma unroll
                for (int rh = 0; rh < 2; rh++) {
                    const int lo = rh * 2;
                    const float4 keep = make_float4(
                        d[mt][4 * P][lo],     d[mt][4 * P][lo + 1],
                        d[mt][4 * P + 1][lo], d[mt][4 * P + 1][lo + 1]);
                    const float4 mine = make_float4(
                        d[mt][4 * P + 2][lo],     d[mt][4 * P + 2][lo + 1],
                        d[mt][4 * P + 3][lo],     d[mt][4 * P + 3][lo + 1]);
                    float4 recv;
                    recv.x = __shfl_xor_sync(0xFFFFFFFFu, mine.x, 16);
                    recv.y = __shfl_xor_sync(0xFFFFFFFFu, mine.y, 16);
                    recv.z = __shfl_xor_sync(0xFFFFFFFFu, mine.z, 16);
                    recv.w = __shfl_xor_sync(0xFFFFFFFFu, mine.w, 16);

                    const int rowLo = rBase + rh * 8 + rsel;
                    *(float4*)&out[(size_t)rowLo * NCOL + colL + (hiGr ? 16 : 0)] =
                        hiGr ? recv : keep;
                    const int rowHi = rowLo + 4;
                    *(float4*)&out[(size_t)rowHi * NCOL + colL + (hiGr ? 0 : 16)] =
                        hiGr ? keep : recv;
                }
            }
        }
    }
}

// ---------------------------------------------------------------------------
extern "C" void kernel_launch(void* const* d_in, const int* in_sizes, int n_in,
                              void* d_out, int out_size)
{
    const float* positions   = (const float*)d_in[0];
    const float* obs_pos     = (const float*)d_in[1];
    const float* poly_dic    = (const float*)d_in[2];
    const float* graph_dic   = (const float*)d_in[3];
    const float* alpha_poly  = (const float*)d_in[4];
    const float* alpha_graph = (const float*)d_in[5];
    const float* S_poly      = (const float*)d_in[6];
    const float* S_graph     = (const float*)d_in[7];
    float* out = (float*)d_out;

    nn_coef_kernel<<<B_Q / 8, 256>>>(positions, obs_pos, poly_dic, graph_dic,
                                     alpha_poly, alpha_graph);

    // grid.x = batch tiles (fast) so 16 CTAs sharing one S tile run adjacently
    dim3 grid(B_Q / BM, NCOL / BN);   // (16, 512)
    opd_kernel<<<grid, 256>>>(S_poly, S_graph, out);
}

// round 15
// speedup vs baseline: 1.2879x; 1.2879x over previous
#include <cuda_runtime.h>
#include <cstdint>

#define B_Q    2048
#define NOBS   2048
#define PP     15
#define GG     21
#define EE     64
#define NCOL   65536          /* D*D */
#define KK     36
#define KPAD   40             /* coef gmem row stride (cols 36..39 zero, unused) */

#define BM 128                /* batch rows per CTA (MMA M) */
#define BN 128                /* S columns per CTA  (MMA N) */

// coef scratch: [b][KPAD] (tf32-rounded)
__device__ float g_coef[B_Q * KPAD];

__device__ __forceinline__ uint32_t f2tf32(float x) {
    uint32_t u;
    asm("cvt.rna.tf32.f32 %0, %1;" : "=r"(u) : "f"(x));
    return u;
}

__device__ __forceinline__ void mma_tf32(float* d, const uint32_t* a,
                                         uint32_t b0, uint32_t b1) {
    asm volatile(
        "mma.sync.aligned.m16n8k8.row.col.f32.tf32.tf32.f32 "
        "{%0,%1,%2,%3}, {%4,%5,%6,%7}, {%8,%9}, {%0,%1,%2,%3};"
        : "+f"(d[0]), "+f"(d[1]), "+f"(d[2]), "+f"(d[3])
        : "r"(a[0]), "r"(a[1]), "r"(a[2]), "r"(a[3]), "r"(b0), "r"(b1));
}
__device__ __forceinline__ void mma_tf32_k4(float* d, uint32_t a0, uint32_t a1,
                                            uint32_t b0) {
    asm volatile(
        "mma.sync.aligned.m16n8k4.row.col.f32.tf32.tf32.f32 "
        "{%0,%1,%2,%3}, {%4,%5}, {%6}, {%0,%1,%2,%3};"
        : "+f"(d[0]), "+f"(d[1]), "+f"(d[2]), "+f"(d[3])
        : "r"(a0), "r"(a1), "r"(b0));
}

// ---------------------------------------------------------------------------
// Kernel 1: warp-per-query 1-NN + alpha mixing -> g_coef[b][KPAD] (tf32-rounded)
// (unchanged from R13)
// ---------------------------------------------------------------------------
__global__ __launch_bounds__(256) void nn_coef_kernel(
    const float* __restrict__ positions, const float* __restrict__ obs_pos,
    const float* __restrict__ poly_dic,  const float* __restrict__ graph_dic,
    const float* __restrict__ alpha_poly, const float* __restrict__ alpha_graph)
{
    __shared__ float2 sObs[NOBS];
    __shared__ float  sAp[PP * PP];
    __shared__ float  sAg[EE * GG];

    const int tid = threadIdx.x;
    for (int i = tid; i < NOBS; i += 256) sObs[i] = ((const float2*)obs_pos)[i];
    for (int i = tid; i < PP * PP; i += 256) sAp[i] = alpha_poly[i];
    for (int i = tid; i < EE * GG; i += 256) sAg[i] = alpha_graph[i];
    __syncthreads();

    const int wid = tid >> 5, lid = tid & 31;
    const int b = blockIdx.x * 8 + wid;          // 256 blocks x 8 warps = 2048 queries
    const float px = positions[2 * b];
    const float py = positions[2 * b + 1];

    float bestD = 3.0e38f; int bestJ = 0;
    for (int j = lid; j < NOBS; j += 32) {
        const float dx = px - sObs[j].x;
        const float dy = py - sObs[j].y;
        const float d2 = dx * dx + dy * dy;
        if (d2 < bestD) { bestD = d2; bestJ = j; }
    }
    // exact argmin, first-index tiebreak: pack (d2bits, idx), min-reduce
    unsigned long long key = ((unsigned long long)__float_as_uint(bestD) << 32) | (unsigned)bestJ;
#pragma unroll
    for (int off = 16; off >= 1; off >>= 1) {
        unsigned long long o = __shfl_xor_sync(0xFFFFFFFFu, key, off);
        if (o < key) key = o;
    }
    const int bi = (int)(key & 0xFFFFFFFFu);

    const float* pd = poly_dic + bi * PP;
    const float* gd = graph_dic + bi * EE;
#pragma unroll
    for (int c = lid; c < KPAD; c += 32) {
        float s = 0.f;
        if (c < PP) {
#pragma unroll
            for (int q = 0; q < PP; q++) s = fmaf(pd[q], sAp[q * PP + c], s);
        } else if (c < KK) {
            const int g = c - PP;
#pragma unroll
            for (int e = 0; e < EE; e++) s = fmaf(gd[e], sAg[e * GG + g], s);
        }
        g_coef[b * KPAD + c] = __uint_as_float(f2tf32(s));
    }
}

// ---------------------------------------------------------------------------
// Kernel 2: out[b][c] = sum_k coef[b][k] * S[k][c] via mma.sync tf32.
//   EXACT R13 structure (123.9us proven: scalar sA, permuted STG.128 epilogue,
//   4 x m16n8k8 + k4 tail, occ 3).
//   Single change: S tile stored as (k, k+4) float2 pairs so B-fragments load
//   with ONE LDS.64 instead of two LDS.32 (same bytes, half the instructions).
//   Pair rows: pr = ks*4+tg -> (S[ks*8+tg], S[ks*8+tg+4]); pr=16+tg -> (S[32+tg], 0).
// ---------------------------------------------------------------------------
#define SA_STRIDE 44          /* banks 12*gr+tg : all 32 distinct */
#define SS2_STRIDE 132        /* float2 stride == 4 mod 16: LDS.64 phase-conflict-free */
#define NPR 20                /* pair rows: 16 full + 4 tail */

__global__ __launch_bounds__(256, 3) void opd_kernel(
    const float* __restrict__ S_poly, const float* __restrict__ S_graph,
    float* __restrict__ out)
{
    __shared__ float  sA[BM][SA_STRIDE];        // coef tile [row][k] (36 used)
    __shared__ float2 sS2[NPR][SS2_STRIDE];     // S tile: pair rows x permuted slots

    const int tid = threadIdx.x;
    const int wid = tid >> 5, lid = tid & 31;
    const int gr  = lid >> 2;                 // lane/4
    const int tg  = lid & 3;                  // lane%4
    const int wm  = wid >> 1;                 // M offset 32*wm
    const int wn  = wid & 1;                  // N offset 64*wn

    const int rowBase = blockIdx.x * BM;      // batch rows
    const int colBase = blockIdx.y * BN;      // S columns

    // ---- load coef tile: 128 rows x 9 float4 (36 floats; gmem stride KPAD)
#pragma unroll
    for (int i = tid; i < BM * 9; i += 256) {
        const int r = i / 9, q = i % 9;
        const float4 v = *(const float4*)&g_coef[(rowBase + r) * KPAD + q * 4];
        *(float4*)&sA[r][q * 4] = v;
    }
    // ---- S tile: 20 pair-rows x 128 cols; two LDG + one permuted STS.64 each
#pragma unroll
    for (int i = tid; i < NPR * BN; i += 256) {
        const int p = i >> 7, g = i & 127;
        float2 v;
        if (p < 16) {
            const int k_lo = (p >> 2) * 8 + (p & 3);   // ks*8 + tg
            const int k_hi = k_lo + 4;
            const float* s0 = (k_lo < PP) ? (S_poly + (size_t)k_lo * NCOL)
                                          : (S_graph + (size_t)(k_lo - PP) * NCOL);
            const float* s1 = (k_hi < PP) ? (S_poly + (size_t)k_hi * NCOL)
                                          : (S_graph + (size_t)(k_hi - PP) * NCOL);
            v.x = __uint_as_float(f2tf32(s0[colBase + g]));
            v.y = __uint_as_float(f2tf32(s1[colBase + g]));
        } else {
            const int k_lo = 32 + (p - 16);            // 32..35, all >= PP
            v.x = __uint_as_float(f2tf32(S_graph[(size_t)(k_lo - PP) * NCOL + colBase + g]));
            v.y = 0.f;
        }
        const int half = g >> 6, l = g & 63;
        const int fp = l >> 4, rem = l & 15;
        const int ptg = rem >> 2, r2 = rem & 3;
        const int s = half * 64 + (fp * 2 + (r2 >> 1)) * 8 + ptg * 2 + (r2 & 1);
        sS2[p][s] = v;
    }
    __syncthreads();

    float d[2][8][4];
#pragma unroll
    for (int mt = 0; mt < 2; mt++)
#pragma unroll
        for (int f = 0; f < 8; f++)
#pragma unroll
            for (int j = 0; j < 4; j++) d[mt][f][j] = 0.f;

    // ---- 4 full k8 steps; B-fragment = one LDS.64 (pair row ks*4+tg)
#pragma unroll
    for (int ks = 0; ks < 4; ks++) {
        const int k0 = ks * 8;
        uint32_t a[2][4];
#pragma unroll
        for (int mt = 0; mt < 2; mt++) {
            const int r0 = wm * 32 + mt * 16 + gr;
            a[mt][0] = __float_as_uint(sA[r0][k0 + tg]);
            a[mt][1] = __float_as_uint(sA[r0 + 8][k0 + tg]);
            a[mt][2] = __float_as_uint(sA[r0][k0 + tg + 4]);
            a[mt][3] = __float_as_uint(sA[r0 + 8][k0 + tg + 4]);
        }
#pragma unroll
        for (int f = 0; f < 8; f++) {
            const int c0 = wn * 64 + f * 8 + gr;
            const float2 q = sS2[ks * 4 + tg][c0];
            const uint32_t b0 = __float_as_uint(q.x);
            const uint32_t b1 = __float_as_uint(q.y);
            mma_tf32(d[0][f], a[0], b0, b1);
            mma_tf32(d[1][f], a[1], b0, b1);
        }
    }
    // ---- k4 tail: k = 32..35 (pair rows 16..19, .x valid, .y zero)
    {
        uint32_t a0[2], a1[2];
#pragma unroll
        for (int mt = 0; mt < 2; mt++) {
            const int r0 = wm * 32 + mt * 16 + gr;
            a0[mt] = __float_as_uint(sA[r0][32 + tg]);
            a1[mt] = __float_as_uint(sA[r0 + 8][32 + tg]);
        }
#pragma unroll
        for (int f = 0; f < 8; f++) {
            const int c0 = wn * 64 + f * 8 + gr;
            const float2 q = sS2[16 + tg][c0];
            const uint32_t b0 = __float_as_uint(q.x);
            mma_tf32_k4(d[0][f], a0[0], a1[0], b0);
            mma_tf32_k4(d[1][f], a0[1], a1[1], b0);
        }
    }

    // ---- epilogue: frag pair (2fp, 2fp+1) -> 4 consecutive cols -> STG.128
#pragma unroll
    for (int mt = 0; mt < 2; mt++) {
        const int row0 = rowBase + wm * 32 + mt * 16 + gr;
#pragma unroll
        for (int fp = 0; fp < 4; fp++) {
            const int col = colBase + wn * 64 + fp * 16 + tg * 4;
            *(float4*)&out[(size_t)row0 * NCOL + col] =
                make_float4(d[mt][2 * fp][0], d[mt][2 * fp][1],
                            d[mt][2 * fp + 1][0], d[mt][2 * fp + 1][1]);
            *(float4*)&out[(size_t)(row0 + 8) * NCOL + col] =
                make_float4(d[mt][2 * fp][2], d[mt][2 * fp][3],
                            d[mt][2 * fp + 1][2], d[mt][2 * fp + 1][3]);
        }
    }
}

// ---------------------------------------------------------------------------
extern "C" void kernel_launch(void* const* d_in, const int* in_sizes, int n_in,
                              void* d_out, int out_size)
{
    const float* positions   = (const float*)d_in[0];
    const float* obs_pos     = (const float*)d_in[1];
    const float* poly_dic    = (const float*)d_in[2];
    const float* graph_dic   = (const float*)d_in[3];
    const float* alpha_poly  = (const float*)d_in[4];
    const float* alpha_graph = (const float*)d_in[5];
    const float* S_poly      = (const float*)d_in[6];
    const float* S_graph     = (const float*)d_in[7];
    float* out = (float*)d_out;

    nn_coef_kernel<<<B_Q / 8, 256>>>(positions, obs_pos, poly_dic, graph_dic,
                                     alpha_poly, alpha_graph);

    // grid.x = batch tiles (fast) so 16 CTAs sharing one S tile run adjacently
    dim3 grid(B_Q / BM, NCOL / BN);   // (16, 512)
    opd_kernel<<<grid, 256>>>(S_poly, S_graph, out);
}